// round 1
// baseline (speedup 1.0000x reference)
#include <cuda_runtime.h>
#include <cuda_bf16.h>
#include <cstdint>
#include <cstddef>

#define BATCH 8
#define NPTS 16384
#define FDIM 6
#define MCENT 128
#define KNN_K 16
#define DOUT 768

// ---------------- scratch (__device__ globals: allowed, no allocation) ----------------
__device__ float4 g_pts[BATCH * NPTS];                     // packed xyzt
__device__ float  g_h1[(size_t)BATCH * NPTS * 256];
__device__ float  g_h2[(size_t)BATCH * NPTS * 512];
__device__ float  g_h3[(size_t)BATCH * NPTS * 768];
__device__ float  g_pf[(size_t)BATCH * NPTS * 768];
__device__ float  g_mind[BATCH * NPTS];
__device__ int    g_fidx[BATCH * MCENT];
__device__ float4 g_cent[BATCH * MCENT];
__device__ int    g_knn[BATCH * MCENT * KNN_K];
__device__ float  g_pooled[BATCH * MCENT * DOUT];
__device__ float  g_t1[BATCH * MCENT * DOUT];
__device__ float  g_tok[BATCH * MCENT * DOUT];
__device__ int    g_rank[BATCH * MCENT];

// ---------------- pack coordinates -> float4 points ----------------
__global__ void pack_pts_kernel(const float* __restrict__ coords) {
    int i = blockIdx.x * blockDim.x + threadIdx.x;
    if (i < BATCH * NPTS) {
        const float* p = coords + (size_t)i * 5;
        g_pts[i] = make_float4(p[1], p[2], p[3], p[4]);
    }
}

// ---------------- layer 0: [B*N,6] @ [6,256] + b, relu ----------------
__global__ void mlp0_kernel(const float* __restrict__ f, const float* __restrict__ W0,
                            const float* __restrict__ b0) {
    int p = blockIdx.x;          // point
    int j = threadIdx.x;         // 256 output cols
    __shared__ float fr[FDIM];
    if (j < FDIM) fr[j] = f[(size_t)p * FDIM + j];
    __syncthreads();
    float acc = b0[j];
#pragma unroll
    for (int k = 0; k < FDIM; k++) acc += fr[k] * W0[k * 256 + j];
    g_h1[(size_t)p * 256 + j] = fmaxf(acc, 0.0f);
}

// ---------------- generic SGEMM: C[M,N] = A[M,K] @ B[K,N] + bias, optional relu ----------------
// Requires M%128==0, N%128==0, K%16==0.
__global__ void __launch_bounds__(256) sgemm_kernel(
    const float* __restrict__ A, const float* __restrict__ Bw,
    const float* __restrict__ bias, float* __restrict__ C,
    int Mdim, int Ndim, int Kdim, int relu)
{
    __shared__ float As[16][128];
    __shared__ float Bs[16][128];
    const int tid = threadIdx.x;
    const int bx = blockIdx.x, by = blockIdx.y;
    const float* Ap = A + (size_t)by * 128 * Kdim;
    const float* Bp = Bw + (size_t)bx * 128;
    const int tc = (tid & 15) * 8;
    const int tr = (tid >> 4) * 8;
    float acc[8][8];
#pragma unroll
    for (int i = 0; i < 8; i++)
#pragma unroll
        for (int j = 0; j < 8; j++) acc[i][j] = 0.0f;

    for (int k0 = 0; k0 < Kdim; k0 += 16) {
#pragma unroll
        for (int i = 0; i < 2; i++) {
            int id = tid + i * 256;          // 0..511
            int r  = id >> 2;                // 0..127
            int c4 = (id & 3) * 4;           // 0,4,8,12
            float4 v = *(const float4*)(Ap + (size_t)r * Kdim + k0 + c4);
            As[c4 + 0][r] = v.x; As[c4 + 1][r] = v.y;
            As[c4 + 2][r] = v.z; As[c4 + 3][r] = v.w;
        }
#pragma unroll
        for (int i = 0; i < 2; i++) {
            int id = tid + i * 256;
            int r  = id >> 5;                // 0..15
            int c4 = (id & 31) * 4;          // 0..124
            *(float4*)&Bs[r][c4] = *(const float4*)(Bp + (size_t)(k0 + r) * Ndim + c4);
        }
        __syncthreads();
#pragma unroll
        for (int kk = 0; kk < 16; kk++) {
            float4 a0 = *(float4*)&As[kk][tr];
            float4 a1 = *(float4*)&As[kk][tr + 4];
            float4 b0 = *(float4*)&Bs[kk][tc];
            float4 b1 = *(float4*)&Bs[kk][tc + 4];
            float a[8] = {a0.x, a0.y, a0.z, a0.w, a1.x, a1.y, a1.z, a1.w};
            float b[8] = {b0.x, b0.y, b0.z, b0.w, b1.x, b1.y, b1.z, b1.w};
#pragma unroll
            for (int i = 0; i < 8; i++)
#pragma unroll
                for (int j = 0; j < 8; j++) acc[i][j] += a[i] * b[j];
        }
        __syncthreads();
    }
    float bv[8];
#pragma unroll
    for (int j = 0; j < 8; j++) bv[j] = bias[(size_t)bx * 128 + tc + j];
    float* Cp = C + ((size_t)by * 128 + tr) * Ndim + (size_t)bx * 128 + tc;
#pragma unroll
    for (int i = 0; i < 8; i++) {
        float4 o0, o1;
        float v;
        v = acc[i][0] + bv[0]; o0.x = relu ? fmaxf(v, 0.f) : v;
        v = acc[i][1] + bv[1]; o0.y = relu ? fmaxf(v, 0.f) : v;
        v = acc[i][2] + bv[2]; o0.z = relu ? fmaxf(v, 0.f) : v;
        v = acc[i][3] + bv[3]; o0.w = relu ? fmaxf(v, 0.f) : v;
        v = acc[i][4] + bv[4]; o1.x = relu ? fmaxf(v, 0.f) : v;
        v = acc[i][5] + bv[5]; o1.y = relu ? fmaxf(v, 0.f) : v;
        v = acc[i][6] + bv[6]; o1.z = relu ? fmaxf(v, 0.f) : v;
        v = acc[i][7] + bv[7]; o1.w = relu ? fmaxf(v, 0.f) : v;
        *(float4*)(Cp + (size_t)i * Ndim) = o0;
        *(float4*)(Cp + (size_t)i * Ndim + 4) = o1;
    }
}

// ---------------- FPS: one block (1024 thr) per batch ----------------
__global__ void __launch_bounds__(1024) fps_kernel() {
    const int b = blockIdx.x;
    const int tid = threadIdx.x;
    const float4* P = g_pts + (size_t)b * NPTS;
    float* mind = g_mind + (size_t)b * NPTS;
    __shared__ float redv[32];
    __shared__ int   redi[32];
    __shared__ int   s_last;
    if (tid == 0) {
        s_last = 0;
        g_fidx[b * MCENT] = 0;
        g_cent[b * MCENT] = P[0];
    }
    __syncthreads();

    for (int it = 1; it < MCENT; it++) {
        int last = s_last;
        float4 q = P[last];
        float bestv = -1.0f;
        int   besti = 0x7fffffff;
#pragma unroll 4
        for (int i = tid; i < NPTS; i += 1024) {
            float4 p = P[i];
            float dx = p.x - q.x, dy = p.y - q.y, dz = p.z - q.z, dw = p.w - q.w;
            float d = dx * dx + dy * dy + dz * dz + dw * dw;
            float md = (it == 1) ? d : fminf(mind[i], d);
            mind[i] = md;
            if (md > bestv || (md == bestv && i < besti)) { bestv = md; besti = i; }
        }
        // warp reduce (lexicographic argmax, lower index wins ties)
#pragma unroll
        for (int off = 16; off > 0; off >>= 1) {
            float ov = __shfl_down_sync(0xffffffffu, bestv, off);
            int   oi = __shfl_down_sync(0xffffffffu, besti, off);
            if (ov > bestv || (ov == bestv && oi < besti)) { bestv = ov; besti = oi; }
        }
        int warp = tid >> 5;
        if ((tid & 31) == 0) { redv[warp] = bestv; redi[warp] = besti; }
        __syncthreads();
        if (tid == 0) {
            float bv = redv[0]; int bi = redi[0];
#pragma unroll
            for (int w = 1; w < 32; w++) {
                if (redv[w] > bv || (redv[w] == bv && redi[w] < bi)) { bv = redv[w]; bi = redi[w]; }
            }
            s_last = bi;
            g_fidx[b * MCENT + it] = bi;
            g_cent[b * MCENT + it] = P[bi];
        }
        __syncthreads();
    }
}

// ---------------- kNN: one block (256 thr) per (b, m) ----------------
__device__ __forceinline__ bool dless(float d1, int i1, float d2, int i2) {
    return (d1 < d2) || (d1 == d2 && i1 < i2);
}

__global__ void __launch_bounds__(256) knn_kernel() {
    const int bm = blockIdx.x;
    const int b = bm / MCENT;
    const int tid = threadIdx.x;
    float4 c = g_cent[bm];
    const float4* P = g_pts + (size_t)b * NPTS;

    float ld[KNN_K];
    int   li[KNN_K];
#pragma unroll
    for (int s = 0; s < KNN_K; s++) { ld[s] = 3.0e38f; li[s] = 0x7fffffff; }

    for (int i = tid; i < NPTS; i += 256) {
        float4 p = P[i];
        float dx = p.x - c.x, dy = p.y - c.y, dz = p.z - c.z, dw = p.w - c.w;
        float d = dx * dx + dy * dy + dz * dz + dw * dw;
        if (dless(d, i, ld[KNN_K - 1], li[KNN_K - 1])) {
            ld[KNN_K - 1] = d; li[KNN_K - 1] = i;
#pragma unroll
            for (int s = KNN_K - 1; s > 0; s--) {
                if (dless(ld[s], li[s], ld[s - 1], li[s - 1])) {
                    float td = ld[s]; ld[s] = ld[s - 1]; ld[s - 1] = td;
                    int   ti = li[s]; li[s] = li[s - 1]; li[s - 1] = ti;
                }
            }
        }
    }

    __shared__ float sd[256][KNN_K];
    __shared__ int   si[256][KNN_K];
    __shared__ float wv[8];
    __shared__ int   wi[8];
    __shared__ float fv;
    __shared__ int   fi;
#pragma unroll
    for (int s = 0; s < KNN_K; s++) { sd[tid][s] = ld[s]; si[tid][s] = li[s]; }
    __syncthreads();

    int pos = 0;
    for (int r = 0; r < KNN_K; r++) {
        float hv = sd[tid][pos];
        int   hi = si[tid][pos];
        float v = hv; int idx = hi;
#pragma unroll
        for (int off = 16; off > 0; off >>= 1) {
            float ov = __shfl_down_sync(0xffffffffu, v, off);
            int   oi = __shfl_down_sync(0xffffffffu, idx, off);
            if (dless(ov, oi, v, idx)) { v = ov; idx = oi; }
        }
        if ((tid & 31) == 0) { wv[tid >> 5] = v; wi[tid >> 5] = idx; }
        __syncthreads();
        if (tid == 0) {
            float bv = wv[0]; int bi = wi[0];
#pragma unroll
            for (int w = 1; w < 8; w++)
                if (dless(wv[w], wi[w], bv, bi)) { bv = wv[w]; bi = wi[w]; }
            fv = bv; fi = bi;
            g_knn[bm * KNN_K + r] = bi;
        }
        __syncthreads();
        if (hi == fi) pos++;
        __syncthreads();
    }
}

// ---------------- gather + max pool ----------------
__global__ void __launch_bounds__(256) gather_maxpool_kernel() {
    const int bm = blockIdx.x;
    const int b = bm / MCENT;
    __shared__ int ks[KNN_K];
    if (threadIdx.x < KNN_K) ks[threadIdx.x] = g_knn[bm * KNN_K + threadIdx.x];
    __syncthreads();
    for (int d = threadIdx.x; d < DOUT; d += 256) {
        float m = -3.0e38f;
#pragma unroll
        for (int k = 0; k < KNN_K; k++) {
            float v = g_pf[((size_t)b * NPTS + ks[k]) * DOUT + d];
            m = fmaxf(m, v);
        }
        g_pooled[(size_t)bm * DOUT + d] = m;
    }
}

// ---------------- stable rank by centroid time ----------------
__global__ void rank_kernel() {
    const int b = blockIdx.x;
    const int i = threadIdx.x;   // 128
    __shared__ float ts[MCENT];
    float t = g_cent[b * MCENT + i].w;
    ts[i] = t;
    __syncthreads();
    int r = 0;
#pragma unroll
    for (int j = 0; j < MCENT; j++) {
        float tj = ts[j];
        r += (tj < t) || (tj == t && j < i);
    }
    g_rank[b * MCENT + i] = r;
}

// ---------------- scatter sorted tokens + centroids ----------------
__global__ void __launch_bounds__(256) scatter_kernel(float* __restrict__ out, long out_size) {
    const int bm = blockIdx.x;
    const int b = bm >> 7;
    const int r = g_rank[bm];
    const size_t dst = ((size_t)b * MCENT + r) * DOUT;
    const float* src = g_tok + (size_t)bm * DOUT;
    for (int d = threadIdx.x; d < DOUT; d += 256)
        if ((long)(dst + d) < out_size) out[dst + d] = src[d];
    if (threadIdx.x == 0) {
        float4 c = g_cent[bm];
        size_t cb = (size_t)BATCH * MCENT * DOUT + ((size_t)b * MCENT + r) * 4;
        if ((long)(cb + 3) < out_size) {
            out[cb + 0] = c.x; out[cb + 1] = c.y; out[cb + 2] = c.z; out[cb + 3] = c.w;
        }
    }
}

__global__ void mask_fill_kernel(float* __restrict__ out, long out_size) {
    size_t base = (size_t)BATCH * MCENT * DOUT + (size_t)BATCH * MCENT * 4;
    size_t i = base + (size_t)blockIdx.x * blockDim.x + threadIdx.x;
    if ((long)i < out_size) out[i] = 1.0f;
}

// ---------------- launch ----------------
extern "C" void kernel_launch(void* const* d_in, const int* in_sizes, int n_in,
                              void* d_out, int out_size) {
    const float* coords = (const float*)d_in[0];
    const float* feats  = (const float*)d_in[1];
    const float* W0 = (const float*)d_in[2];  const float* b0 = (const float*)d_in[3];
    const float* W1 = (const float*)d_in[4];  const float* b1 = (const float*)d_in[5];
    const float* W2 = (const float*)d_in[6];  const float* b2 = (const float*)d_in[7];
    const float* W3 = (const float*)d_in[8];  const float* b3 = (const float*)d_in[9];
    const float* Wn0 = (const float*)d_in[10]; const float* bn0 = (const float*)d_in[11];
    const float* Wn1 = (const float*)d_in[12]; const float* bn1 = (const float*)d_in[13];
    float* out = (float*)d_out;

    float *h1, *h2, *h3, *pf, *pooled, *t1, *tok;
    cudaGetSymbolAddress((void**)&h1, g_h1);
    cudaGetSymbolAddress((void**)&h2, g_h2);
    cudaGetSymbolAddress((void**)&h3, g_h3);
    cudaGetSymbolAddress((void**)&pf, g_pf);
    cudaGetSymbolAddress((void**)&pooled, g_pooled);
    cudaGetSymbolAddress((void**)&t1, g_t1);
    cudaGetSymbolAddress((void**)&tok, g_tok);

    const int BN = BATCH * NPTS;        // 131072
    const int BM = BATCH * MCENT;       // 1024

    // geometry path
    pack_pts_kernel<<<(BN + 255) / 256, 256>>>(coords);
    fps_kernel<<<BATCH, 1024>>>();
    knn_kernel<<<BM, 256>>>();

    // feature path (per-point MLP)
    mlp0_kernel<<<BN, 256>>>(feats, W0, b0);
    {
        dim3 g(512 / 128, BN / 128);
        sgemm_kernel<<<g, 256>>>(h1, W1, b1, h2, BN, 512, 256, 1);
    }
    {
        dim3 g(768 / 128, BN / 128);
        sgemm_kernel<<<g, 256>>>(h2, W2, b2, h3, BN, 768, 512, 1);
    }
    {
        dim3 g(768 / 128, BN / 128);
        sgemm_kernel<<<g, 256>>>(h3, W3, b3, pf, BN, 768, 768, 0);
    }

    // pool + token MLP
    gather_maxpool_kernel<<<BM, 256>>>();
    {
        dim3 g(768 / 128, BM / 128);
        sgemm_kernel<<<g, 256>>>(pooled, Wn0, bn0, t1, BM, 768, 768, 1);
        sgemm_kernel<<<g, 256>>>(t1, Wn1, bn1, tok, BM, 768, 768, 0);
    }

    // sort by centroid time, write outputs
    rank_kernel<<<BATCH, MCENT>>>();
    scatter_kernel<<<BM, 256>>>(out, (long)out_size);
    long maskBase = (long)BATCH * MCENT * DOUT + (long)BATCH * MCENT * 4;
    long rem = (long)out_size - maskBase;
    if (rem > 0) {
        int blocks = (int)((rem + 255) / 256);
        mask_fill_kernel<<<blocks, 256>>>(out, (long)out_size);
    }
}

// round 2
// speedup vs baseline: 2.8082x; 2.8082x over previous
#include <cuda_runtime.h>
#include <cuda_bf16.h>
#include <cstdint>
#include <cstddef>

#define BATCH 8
#define NPTS 16384
#define FDIM 6
#define MCENT 128
#define KNN_K 16
#define DOUT 768

// ---------------- scratch ----------------
__device__ float4 g_pts[BATCH * NPTS];
__device__ float  g_h1[(size_t)BATCH * NPTS * 256];
__device__ float  g_h2[(size_t)BATCH * NPTS * 512];
__device__ float  g_h3[(size_t)BATCH * NPTS * 768];
__device__ float  g_pf[(size_t)BATCH * NPTS * 768];
__device__ float  g_mind[BATCH * NPTS];
__device__ int    g_fidx[BATCH * MCENT];
__device__ float4 g_cent[BATCH * MCENT];
__device__ int    g_knn[BATCH * MCENT * KNN_K];
__device__ float  g_pooled[BATCH * MCENT * DOUT];
__device__ float  g_t1[BATCH * MCENT * DOUT];
__device__ float  g_tok[BATCH * MCENT * DOUT];
__device__ int    g_rank[BATCH * MCENT];
// tf32-rounded weights
__device__ float  g_w1r[256 * 512];
__device__ float  g_w2r[512 * 768];
__device__ float  g_w3r[768 * 768];
__device__ float  g_wn0r[768 * 768];
__device__ float  g_wn1r[768 * 768];

__device__ __forceinline__ float rtf32(float v) {
    uint32_t u;
    asm("cvt.rna.tf32.f32 %0, %1;" : "=r"(u) : "f"(v));
    return __uint_as_float(u);
}

// ---------------- pack coordinates -> float4 points ----------------
__global__ void pack_pts_kernel(const float* __restrict__ coords) {
    int i = blockIdx.x * blockDim.x + threadIdx.x;
    if (i < BATCH * NPTS) {
        const float* p = coords + (size_t)i * 5;
        g_pts[i] = make_float4(p[1], p[2], p[3], p[4]);
    }
}

// ---------------- round weights to tf32 ----------------
__global__ void round_w_kernel(const float* __restrict__ src, float* __restrict__ dst, int n) {
    int i = blockIdx.x * blockDim.x + threadIdx.x;
    if (i < n) dst[i] = rtf32(src[i]);
}

// ---------------- layer 0: [B*N,6] @ [6,256] + b, relu, tf32-rounded output ----------------
__global__ void __launch_bounds__(256) mlp0_kernel(const float* __restrict__ f,
                                                   const float* __restrict__ W0,
                                                   const float* __restrict__ b0) {
    __shared__ float w[FDIM * 256];
    __shared__ float sb[256];
    int tid = threadIdx.x;
#pragma unroll
    for (int i = 0; i < FDIM; i++) w[i * 256 + tid] = W0[i * 256 + tid];
    sb[tid] = b0[tid];
    __syncthreads();
    int p0 = blockIdx.x * 32;
    for (int pp = 0; pp < 32; pp++) {
        int p = p0 + pp;
        const float* fp = f + (size_t)p * FDIM;
        float acc = sb[tid];
#pragma unroll
        for (int k = 0; k < FDIM; k++) acc += fp[k] * w[k * 256 + tid];
        g_h1[(size_t)p * 256 + tid] = rtf32(fmaxf(acc, 0.0f));
    }
}

// ---------------- TF32 tensor-core GEMM ----------------
// C[M,N] = A[M,K] @ B[K,N] + bias ; flags: 1=relu, 2=round output to tf32
// Requires M%128==0, N%128==0, K%32==0. Inputs must be tf32-rounded for full precision.
#define GF_RELU 1
#define GF_ROUND 2

__device__ __forceinline__ void mma_tf32(float* c, const uint32_t* a, const uint32_t* b) {
    asm volatile(
        "mma.sync.aligned.m16n8k8.row.col.f32.tf32.tf32.f32 "
        "{%0,%1,%2,%3}, {%4,%5,%6,%7}, {%8,%9}, {%0,%1,%2,%3};\n"
        : "+f"(c[0]), "+f"(c[1]), "+f"(c[2]), "+f"(c[3])
        : "r"(a[0]), "r"(a[1]), "r"(a[2]), "r"(a[3]), "r"(b[0]), "r"(b[1]));
}

__device__ __forceinline__ void cp16(void* dst, const void* src) {
    uint32_t d = (uint32_t)__cvta_generic_to_shared(dst);
    asm volatile("cp.async.cg.shared.global [%0], [%1], 16;\n" :: "r"(d), "l"(src));
}
__device__ __forceinline__ void cp_commit() { asm volatile("cp.async.commit_group;\n"); }
template <int N>
__device__ __forceinline__ void cp_wait() { asm volatile("cp.async.wait_group %0;\n" :: "n"(N)); }

#define AS_STRIDE 36
#define BS_STRIDE 132
#define AS_SZ (128 * AS_STRIDE)   // 4608 floats per stage
#define BS_SZ (32 * BS_STRIDE)    // 4224 floats per stage
#define GEMM_SMEM ((2 * AS_SZ + 2 * BS_SZ) * 4)  // 70656 bytes

__global__ void __launch_bounds__(128, 2) tf32gemm_kernel(
    const float* __restrict__ A, const float* __restrict__ Bw,
    const float* __restrict__ bias, float* __restrict__ C,
    int Mdim, int Ndim, int Kdim, int flags)
{
    extern __shared__ float smem[];
    float* As = smem;                   // [2][128][36]
    float* Bs = smem + 2 * AS_SZ;       // [2][32][132]

    const int tid = threadIdx.x;
    const int wid = tid >> 5, lane = tid & 31;
    const int grp = lane >> 2, tig = lane & 3;
    const int warp_m = (wid >> 1) * 64;
    const int warp_n = (wid & 1) * 64;
    const int rowBase = blockIdx.y * 128;
    const int colBase = blockIdx.x * 128;

    float acc[4][8][4];
#pragma unroll
    for (int i = 0; i < 4; i++)
#pragma unroll
        for (int j = 0; j < 8; j++)
#pragma unroll
            for (int t = 0; t < 4; t++) acc[i][j][t] = 0.0f;

    const int nk = Kdim >> 5;

    // stage load: s in {0,1}, k0 = k offset
#define LOAD_STAGE(s, k0)                                                          \
    {                                                                              \
        float* as = As + (s) * AS_SZ;                                              \
        float* bs = Bs + (s) * BS_SZ;                                              \
        _Pragma("unroll")                                                          \
        for (int i = 0; i < 8; i++) {                                              \
            int idx = i * 128 + tid;                                               \
            int r = idx >> 3, c4 = (idx & 7) << 2;                                 \
            cp16(as + r * AS_STRIDE + c4,                                          \
                 A + (size_t)(rowBase + r) * Kdim + (k0) + c4);                    \
        }                                                                          \
        _Pragma("unroll")                                                          \
        for (int i = 0; i < 8; i++) {                                              \
            int idx = i * 128 + tid;                                               \
            int r = idx >> 5, c4 = (idx & 31) << 2;                                \
            cp16(bs + r * BS_STRIDE + c4,                                          \
                 Bw + (size_t)((k0) + r) * Ndim + colBase + c4);                   \
        }                                                                          \
    }

    LOAD_STAGE(0, 0);
    cp_commit();
    LOAD_STAGE(1, 32);
    cp_commit();

    for (int kt = 0; kt < nk; kt++) {
        cp_wait<1>();
        __syncthreads();
        const int s = kt & 1;
        const float* as = As + s * AS_SZ;
        const float* bs = Bs + s * BS_SZ;
#pragma unroll
        for (int k8 = 0; k8 < 4; k8++) {
            const int k0 = k8 * 8;
            uint32_t af[4][4];
            uint32_t bf[8][2];
#pragma unroll
            for (int mt = 0; mt < 4; mt++) {
                const float* ap = as + (size_t)(warp_m + mt * 16 + grp) * AS_STRIDE + k0 + tig;
                af[mt][0] = __float_as_uint(ap[0]);
                af[mt][1] = __float_as_uint(ap[8 * AS_STRIDE]);
                af[mt][2] = __float_as_uint(ap[4]);
                af[mt][3] = __float_as_uint(ap[8 * AS_STRIDE + 4]);
            }
#pragma unroll
            for (int nt = 0; nt < 8; nt++) {
                const float* bp = bs + (size_t)(k0 + tig) * BS_STRIDE + warp_n + nt * 8 + grp;
                bf[nt][0] = __float_as_uint(bp[0]);
                bf[nt][1] = __float_as_uint(bp[4 * BS_STRIDE]);
            }
#pragma unroll
            for (int mt = 0; mt < 4; mt++)
#pragma unroll
                for (int nt = 0; nt < 8; nt++)
                    mma_tf32(acc[mt][nt], af[mt], bf[nt]);
        }
        __syncthreads();
        if (kt + 2 < nk) LOAD_STAGE(s, (kt + 2) * 32);
        cp_commit();
    }

    // epilogue
    const int relu = flags & GF_RELU;
    const int rnd = flags & GF_ROUND;
#pragma unroll
    for (int nt = 0; nt < 8; nt++) {
        const int cc = colBase + warp_n + nt * 8 + 2 * tig;
        const float bv0 = bias[cc];
        const float bv1 = bias[cc + 1];
#pragma unroll
        for (int mt = 0; mt < 4; mt++) {
            const int r0 = rowBase + warp_m + mt * 16 + grp;
            float v0 = acc[mt][nt][0] + bv0;
            float v1 = acc[mt][nt][1] + bv1;
            float v2 = acc[mt][nt][2] + bv0;
            float v3 = acc[mt][nt][3] + bv1;
            if (relu) {
                v0 = fmaxf(v0, 0.f); v1 = fmaxf(v1, 0.f);
                v2 = fmaxf(v2, 0.f); v3 = fmaxf(v3, 0.f);
            }
            if (rnd) {
                v0 = rtf32(v0); v1 = rtf32(v1);
                v2 = rtf32(v2); v3 = rtf32(v3);
            }
            *(float2*)(C + (size_t)r0 * Ndim + cc) = make_float2(v0, v1);
            *(float2*)(C + (size_t)(r0 + 8) * Ndim + cc) = make_float2(v2, v3);
        }
    }
}

// ---------------- FPS: one block (1024 thr) per batch ----------------
__global__ void __launch_bounds__(1024) fps_kernel() {
    const int b = blockIdx.x;
    const int tid = threadIdx.x;
    const float4* P = g_pts + (size_t)b * NPTS;
    float* mind = g_mind + (size_t)b * NPTS;
    __shared__ float redv[32];
    __shared__ int   redi[32];
    __shared__ int   s_last;
    if (tid == 0) {
        s_last = 0;
        g_fidx[b * MCENT] = 0;
        g_cent[b * MCENT] = P[0];
    }
    __syncthreads();

    for (int it = 1; it < MCENT; it++) {
        int last = s_last;
        float4 q = P[last];
        float bestv = -1.0f;
        int   besti = 0x7fffffff;
#pragma unroll 4
        for (int i = tid; i < NPTS; i += 1024) {
            float4 p = P[i];
            float dx = p.x - q.x, dy = p.y - q.y, dz = p.z - q.z, dw = p.w - q.w;
            float d = dx * dx + dy * dy + dz * dz + dw * dw;
            float md = (it == 1) ? d : fminf(mind[i], d);
            mind[i] = md;
            if (md > bestv || (md == bestv && i < besti)) { bestv = md; besti = i; }
        }
#pragma unroll
        for (int off = 16; off > 0; off >>= 1) {
            float ov = __shfl_down_sync(0xffffffffu, bestv, off);
            int   oi = __shfl_down_sync(0xffffffffu, besti, off);
            if (ov > bestv || (ov == bestv && oi < besti)) { bestv = ov; besti = oi; }
        }
        int warp = tid >> 5;
        if ((tid & 31) == 0) { redv[warp] = bestv; redi[warp] = besti; }
        __syncthreads();
        if (tid == 0) {
            float bv = redv[0]; int bi = redi[0];
#pragma unroll
            for (int w = 1; w < 32; w++) {
                if (redv[w] > bv || (redv[w] == bv && redi[w] < bi)) { bv = redv[w]; bi = redi[w]; }
            }
            s_last = bi;
            g_fidx[b * MCENT + it] = bi;
            g_cent[b * MCENT + it] = P[bi];
        }
        __syncthreads();
    }
}

// ---------------- kNN ----------------
__device__ __forceinline__ bool dless(float d1, int i1, float d2, int i2) {
    return (d1 < d2) || (d1 == d2 && i1 < i2);
}

__global__ void __launch_bounds__(256) knn_kernel() {
    const int bm = blockIdx.x;
    const int b = bm / MCENT;
    const int tid = threadIdx.x;
    float4 c = g_cent[bm];
    const float4* P = g_pts + (size_t)b * NPTS;

    float ld[KNN_K];
    int   li[KNN_K];
#pragma unroll
    for (int s = 0; s < KNN_K; s++) { ld[s] = 3.0e38f; li[s] = 0x7fffffff; }

    for (int i = tid; i < NPTS; i += 256) {
        float4 p = P[i];
        float dx = p.x - c.x, dy = p.y - c.y, dz = p.z - c.z, dw = p.w - c.w;
        float d = dx * dx + dy * dy + dz * dz + dw * dw;
        if (dless(d, i, ld[KNN_K - 1], li[KNN_K - 1])) {
            ld[KNN_K - 1] = d; li[KNN_K - 1] = i;
#pragma unroll
            for (int s = KNN_K - 1; s > 0; s--) {
                if (dless(ld[s], li[s], ld[s - 1], li[s - 1])) {
                    float td = ld[s]; ld[s] = ld[s - 1]; ld[s - 1] = td;
                    int   ti = li[s]; li[s] = li[s - 1]; li[s - 1] = ti;
                }
            }
        }
    }

    __shared__ float sd[256][KNN_K];
    __shared__ int   si[256][KNN_K];
    __shared__ float wv[8];
    __shared__ int   wi[8];
    __shared__ int   fi;
#pragma unroll
    for (int s = 0; s < KNN_K; s++) { sd[tid][s] = ld[s]; si[tid][s] = li[s]; }
    __syncthreads();

    int pos = 0;
    for (int r = 0; r < KNN_K; r++) {
        float hv = sd[tid][pos];
        int   hi = si[tid][pos];
        float v = hv; int idx = hi;
#pragma unroll
        for (int off = 16; off > 0; off >>= 1) {
            float ov = __shfl_down_sync(0xffffffffu, v, off);
            int   oi = __shfl_down_sync(0xffffffffu, idx, off);
            if (dless(ov, oi, v, idx)) { v = ov; idx = oi; }
        }
        if ((tid & 31) == 0) { wv[tid >> 5] = v; wi[tid >> 5] = idx; }
        __syncthreads();
        if (tid == 0) {
            float bv = wv[0]; int bi = wi[0];
#pragma unroll
            for (int w = 1; w < 8; w++)
                if (dless(wv[w], wi[w], bv, bi)) { bv = wv[w]; bi = wi[w]; }
            fi = bi;
            g_knn[bm * KNN_K + r] = bi;
        }
        __syncthreads();
        if (hi == fi) pos++;
        __syncthreads();
    }
}

// ---------------- gather + max pool (tf32-rounded output) ----------------
__global__ void __launch_bounds__(256) gather_maxpool_kernel() {
    const int bm = blockIdx.x;
    const int b = bm / MCENT;
    __shared__ int ks[KNN_K];
    if (threadIdx.x < KNN_K) ks[threadIdx.x] = g_knn[bm * KNN_K + threadIdx.x];
    __syncthreads();
    for (int d = threadIdx.x; d < DOUT; d += 256) {
        float m = -3.0e38f;
#pragma unroll
        for (int k = 0; k < KNN_K; k++) {
            float v = g_pf[((size_t)b * NPTS + ks[k]) * DOUT + d];
            m = fmaxf(m, v);
        }
        g_pooled[(size_t)bm * DOUT + d] = rtf32(m);
    }
}

// ---------------- stable rank by centroid time ----------------
__global__ void rank_kernel() {
    const int b = blockIdx.x;
    const int i = threadIdx.x;
    __shared__ float ts[MCENT];
    float t = g_cent[b * MCENT + i].w;
    ts[i] = t;
    __syncthreads();
    int r = 0;
#pragma unroll
    for (int j = 0; j < MCENT; j++) {
        float tj = ts[j];
        r += (tj < t) || (tj == t && j < i);
    }
    g_rank[b * MCENT + i] = r;
}

// ---------------- scatter sorted tokens + centroids ----------------
__global__ void __launch_bounds__(256) scatter_kernel(float* __restrict__ out, long out_size) {
    const int bm = blockIdx.x;
    const int b = bm >> 7;
    const int r = g_rank[bm];
    const size_t dst = ((size_t)b * MCENT + r) * DOUT;
    const float* src = g_tok + (size_t)bm * DOUT;
    for (int d = threadIdx.x; d < DOUT; d += 256)
        if ((long)(dst + d) < out_size) out[dst + d] = src[d];
    if (threadIdx.x == 0) {
        float4 c = g_cent[bm];
        size_t cb = (size_t)BATCH * MCENT * DOUT + ((size_t)b * MCENT + r) * 4;
        if ((long)(cb + 3) < out_size) {
            out[cb + 0] = c.x; out[cb + 1] = c.y; out[cb + 2] = c.z; out[cb + 3] = c.w;
        }
    }
}

__global__ void mask_fill_kernel(float* __restrict__ out, long out_size) {
    size_t base = (size_t)BATCH * MCENT * DOUT + (size_t)BATCH * MCENT * 4;
    size_t i = base + (size_t)blockIdx.x * blockDim.x + threadIdx.x;
    if ((long)i < out_size) out[i] = 1.0f;
}

// ---------------- launch ----------------
extern "C" void kernel_launch(void* const* d_in, const int* in_sizes, int n_in,
                              void* d_out, int out_size) {
    const float* coords = (const float*)d_in[0];
    const float* feats  = (const float*)d_in[1];
    const float* W0 = (const float*)d_in[2];  const float* b0 = (const float*)d_in[3];
    const float* W1 = (const float*)d_in[4];  const float* b1 = (const float*)d_in[5];
    const float* W2 = (const float*)d_in[6];  const float* b2 = (const float*)d_in[7];
    const float* W3 = (const float*)d_in[8];  const float* b3 = (const float*)d_in[9];
    const float* Wn0 = (const float*)d_in[10]; const float* bn0 = (const float*)d_in[11];
    const float* Wn1 = (const float*)d_in[12]; const float* bn1 = (const float*)d_in[13];
    float* out = (float*)d_out;

    float *h1, *h2, *h3, *pf, *pooled, *t1, *tok;
    float *w1r, *w2r, *w3r, *wn0r, *wn1r;
    cudaGetSymbolAddress((void**)&h1, g_h1);
    cudaGetSymbolAddress((void**)&h2, g_h2);
    cudaGetSymbolAddress((void**)&h3, g_h3);
    cudaGetSymbolAddress((void**)&pf, g_pf);
    cudaGetSymbolAddress((void**)&pooled, g_pooled);
    cudaGetSymbolAddress((void**)&t1, g_t1);
    cudaGetSymbolAddress((void**)&tok, g_tok);
    cudaGetSymbolAddress((void**)&w1r, g_w1r);
    cudaGetSymbolAddress((void**)&w2r, g_w2r);
    cudaGetSymbolAddress((void**)&w3r, g_w3r);
    cudaGetSymbolAddress((void**)&wn0r, g_wn0r);
    cudaGetSymbolAddress((void**)&wn1r, g_wn1r);

    cudaFuncSetAttribute(tf32gemm_kernel, cudaFuncAttributeMaxDynamicSharedMemorySize, GEMM_SMEM);

    const int BN = BATCH * NPTS;        // 131072
    const int BM = BATCH * MCENT;       // 1024

    // geometry path
    pack_pts_kernel<<<(BN + 255) / 256, 256>>>(coords);
    fps_kernel<<<BATCH, 1024>>>();
    knn_kernel<<<BM, 256>>>();

    // round weights to tf32
    round_w_kernel<<<(256 * 512 + 255) / 256, 256>>>(W1, w1r, 256 * 512);
    round_w_kernel<<<(512 * 768 + 255) / 256, 256>>>(W2, w2r, 512 * 768);
    round_w_kernel<<<(768 * 768 + 255) / 256, 256>>>(W3, w3r, 768 * 768);
    round_w_kernel<<<(768 * 768 + 255) / 256, 256>>>(Wn0, wn0r, 768 * 768);
    round_w_kernel<<<(768 * 768 + 255) / 256, 256>>>(Wn1, wn1r, 768 * 768);

    // feature path (per-point MLP)
    mlp0_kernel<<<BN / 32, 256>>>(feats, W0, b0);
    {
        dim3 g(512 / 128, BN / 128);
        tf32gemm_kernel<<<g, 128, GEMM_SMEM>>>(h1, w1r, b1, h2, BN, 512, 256, GF_RELU | GF_ROUND);
    }
    {
        dim3 g(768 / 128, BN / 128);
        tf32gemm_kernel<<<g, 128, GEMM_SMEM>>>(h2, w2r, b2, h3, BN, 768, 512, GF_RELU | GF_ROUND);
    }
    {
        dim3 g(768 / 128, BN / 128);
        tf32gemm_kernel<<<g, 128, GEMM_SMEM>>>(h3, w3r, b3, pf, BN, 768, 768, 0);
    }

    // pool + token MLP
    gather_maxpool_kernel<<<BM, 256>>>();
    {
        dim3 g(768 / 128, BM / 128);
        tf32gemm_kernel<<<g, 128, GEMM_SMEM>>>(pooled, wn0r, bn0, t1, BM, 768, 768, GF_RELU | GF_ROUND);
        tf32gemm_kernel<<<g, 128, GEMM_SMEM>>>(t1, wn1r, bn1, tok, BM, 768, 768, 0);
    }

    // sort by centroid time, write outputs
    rank_kernel<<<BATCH, MCENT>>>();
    scatter_kernel<<<BM, 256>>>(out, (long)out_size);
    long maskBase = (long)BATCH * MCENT * DOUT + (long)BATCH * MCENT * 4;
    long rem = (long)out_size - maskBase;
    if (rem > 0) {
        int blocks = (int)((rem + 255) / 256);
        mask_fill_kernel<<<blocks, 256>>>(out, (long)out_size);
    }
}